// round 17
// baseline (speedup 1.0000x reference)
#include <cuda_runtime.h>
#include <cstdint>

#define B_    64
#define S_    4096
#define F_    64
#define G4_   256   // 4 * F_

// ---------------- scratch (no cudaMalloc allowed) ----------------
__device__ float g_bufA[(size_t)B_ * S_ * F_];    // conv0 out / conv2 out
__device__ float g_bufB[(size_t)B_ * S_ * F_];    // conv1 out
__device__ float g_xw0[(size_t)B_ * S_ * G4_];    // layer0 gate pre-activations
__device__ float g_cfinal[B_ * F_];

typedef unsigned long long ull;

// ---------------- packed f32x2 helpers (sm_103a FFMA2 path) ----------------
__device__ __forceinline__ ull fma2(ull a, ull b, ull c) {
    ull d;
    asm("fma.rn.f32x2 %0, %1, %2, %3;" : "=l"(d) : "l"(a), "l"(b), "l"(c));
    return d;
}
__device__ __forceinline__ ull add2(ull a, ull b) {
    ull d;
    asm("add.rn.f32x2 %0, %1, %2;" : "=l"(d) : "l"(a), "l"(b));
    return d;
}
__device__ __forceinline__ ull dup2(float a) {
    ull d;
    asm("mov.b64 %0, {%1, %1};" : "=l"(d) : "f"(a));
    return d;
}
__device__ __forceinline__ ull pk2(float lo, float hi) {
    ull d;
    asm("mov.b64 %0, {%1, %2};" : "=l"(d) : "f"(lo), "f"(hi));
    return d;
}
__device__ __forceinline__ float2 upk2(ull v) {
    float2 r;
    asm("mov.b64 {%0, %1}, %2;" : "=f"(r.x), "=f"(r.y) : "l"(v));
    return r;
}

// HW tanh.approx (single MUFU)
__device__ __forceinline__ float tanh_fast(float x) {
    float r;
    asm("tanh.approx.f32 %0, %1;" : "=f"(r) : "f"(x));
    return r;
}
__device__ __forceinline__ float sig_fast(float x) {
    return fmaf(0.5f, tanh_fast(0.5f * x), 0.5f);
}

// ---------------------------------------------------------------------------
// Fused conv1d / GEMM kernel. TK is the K-slab width:
//   KW=3 convs: TK=16 (48 regs, high occupancy — TK=32 blew regs to 129)
//   KW=1 GEMM:  TK=32 (verified 316->246us)
// ---------------------------------------------------------------------------
template <int KW, bool RELU, int TK>
__global__ void __launch_bounds__(256)
conv_gemm(const float* __restrict__ xin, const float* __restrict__ w,
          const float* __restrict__ bias, float* __restrict__ out,
          int Cin, int Cout) {
    constexpr int PAD = KW / 2;
    constexpr int RX = 64 + KW - 1;

    __shared__ __align__(16) float xs[66][TK];
    __shared__ __align__(16) float ws[KW][TK][64];

    const int tid = threadIdx.x;
    const int tx = tid & 15;
    const int ty = tid >> 4;
    const int s0 = blockIdx.x * 64;
    const int co0 = blockIdx.y * 64;
    const int b = blockIdx.z;

    const float* xb = xin + (size_t)b * S_ * Cin;

    ull a01[4], a23[4];
#pragma unroll
    for (int i = 0; i < 4; i++) { a01[i] = 0ull; a23[i] = 0ull; }

    for (int ck = 0; ck < Cin; ck += TK) {
        __syncthreads();
        for (int idx = tid; idx < RX * TK; idx += 256) {
            int r = idx / TK, k = idx % TK;
            int sg = s0 + r - PAD;
            float v = 0.0f;
            if (sg >= 0 && sg < S_) v = xb[(size_t)sg * Cin + ck + k];
            xs[r][k] = v;
        }
        for (int idx = tid; idx < KW * TK * 64; idx += 256) {
            int c = idx & 63, k = (idx >> 6) % TK, dk = idx / (64 * TK);
            ws[dk][k][c] = w[((size_t)dk * Cin + (ck + k)) * Cout + co0 + c];
        }
        __syncthreads();

#pragma unroll
        for (int dk = 0; dk < KW; dk++) {
#pragma unroll
            for (int k = 0; k < TK; k++) {
                ulonglong2 wv =
                    *reinterpret_cast<const ulonglong2*>(&ws[dk][k][tx << 2]);
#pragma unroll
                for (int i = 0; i < 4; i++) {
                    ull av = dup2(xs[ty * 4 + i + dk][k]);
                    a01[i] = fma2(av, wv.x, a01[i]);
                    a23[i] = fma2(av, wv.y, a23[i]);
                }
            }
        }
    }

    const int c0 = co0 + (tx << 2);
    const float bb0 = bias[c0 + 0], bb1 = bias[c0 + 1];
    const float bb2 = bias[c0 + 2], bb3 = bias[c0 + 3];
#pragma unroll
    for (int i = 0; i < 4; i++) {
        float2 v01 = upk2(a01[i]);
        float2 v23 = upk2(a23[i]);
        float4 o;
        o.x = v01.x + bb0; o.y = v01.y + bb1;
        o.z = v23.x + bb2; o.w = v23.y + bb3;
        if (RELU) {
            o.x = fmaxf(o.x, 0.0f); o.y = fmaxf(o.y, 0.0f);
            o.z = fmaxf(o.z, 0.0f); o.w = fmaxf(o.w, 0.0f);
        }
        int sg = s0 + ty * 4 + i;
        *reinterpret_cast<float4*>(&out[((size_t)b * S_ + sg) * Cout + c0]) = o;
    }
}

// ---------------------------------------------------------------------------
// Fully fused 2-layer LSTM: ONE CTA per batch, 384 threads, both layers in
// lockstep (L1 lags L0 by 2 steps). NO cross-CTA communication — fully
// deterministic, unlike the 2-kernel pipe whose replays raced on stale flags.
//   threads 0..255  (L0): gate col g; fused Wh0.h0 + Wx1.h0 dots (shared h
//                         loads, 64 fma2, weights wP=Wh0col, wQ=Wx1col).
//   threads 256..383(L1): two gate cols (i, i+128); two Wh1 dots over SHARED
//                         h1 loads (64 fma2, weights wP/wQ = the 2 columns).
// Wx1 partials flow through parity-2 SMEM xbuf; h0/h1 double-buffered.
// 2 barriers per step cover BOTH layers.
// ---------------------------------------------------------------------------
__global__ void __launch_bounds__(384, 1)
lstm_fused(const float* __restrict__ xw0, const float* __restrict__ Wh0,
           const float* __restrict__ Wx1, const float* __restrict__ b1v,
           const float* __restrict__ Wh1, float* __restrict__ c_final) {
    const int b = blockIdx.x;
    const int tid = threadIdx.x;
    const bool isL0 = tid < 256;

    __shared__ __align__(16) float h0buf[2][F_];
    __shared__ __align__(16) float h1buf[2][F_];
    __shared__ float xbuf[2][G4_];
    __shared__ float gbuf0[G4_];
    __shared__ float gbuf1[G4_];

    ull wP[32], wQ[32];                 // role-dependent contents (shared regs)
    float b1a = 0.0f, b1b = 0.0f;
    int g = 0, i = 0, gtype = 0;
    const float* xwb = nullptr;
    float xwbuf[4] = {0.0f, 0.0f, 0.0f, 0.0f};

    if (isL0) {
        g = tid; gtype = g >> 6;
#pragma unroll
        for (int k2 = 0; k2 < 32; k2++) {
            wP[k2] = pk2(Wh0[(size_t)(2 * k2) * G4_ + g],
                         Wh0[(size_t)(2 * k2 + 1) * G4_ + g]);
            wQ[k2] = pk2(Wx1[(size_t)(2 * k2) * G4_ + g],
                         Wx1[(size_t)(2 * k2 + 1) * G4_ + g]);
        }
        xwb = xw0 + (size_t)b * S_ * G4_ + g;
#pragma unroll
        for (int j = 0; j < 4; j++) xwbuf[j] = xwb[(size_t)j * G4_];
        if (g < F_) {
            h0buf[0][g] = 0.0f; h0buf[1][g] = 0.0f;
            h1buf[0][g] = 0.0f; h1buf[1][g] = 0.0f;
        }
    } else {
        i = tid - 256;                  // 0..127; owns gate cols i and i+128
#pragma unroll
        for (int k2 = 0; k2 < 32; k2++) {
            wP[k2] = pk2(Wh1[(size_t)(2 * k2) * G4_ + i],
                         Wh1[(size_t)(2 * k2 + 1) * G4_ + i]);
            wQ[k2] = pk2(Wh1[(size_t)(2 * k2) * G4_ + i + 128],
                         Wh1[(size_t)(2 * k2 + 1) * G4_ + i + 128]);
        }
        b1a = b1v[i];
        b1b = b1v[i + 128];
    }
    float c_reg = 0.0f;
    __syncthreads();

    for (int t0 = 0; t0 < S_ + 4; t0 += 4) {
#pragma unroll
        for (int j = 0; j < 4; j++) {
            const int t = t0 + j;
            if (isL0) {
                if (t <= S_) {
                    // h0[t-1] lives in h0buf[(t+1)&1]
                    const ulonglong2* h4 =
                        reinterpret_cast<const ulonglong2*>(h0buf[(t + 1) & 1]);
                    ull a0 = 0, a1 = 0, a2 = 0, a3 = 0;
                    ull q0 = 0, q1 = 0, q2 = 0, q3 = 0;
#pragma unroll
                    for (int k4 = 0; k4 < 16; k4 += 2) {
                        ulonglong2 hA = h4[k4];
                        ulonglong2 hB = h4[k4 + 1];
                        a0 = fma2(hA.x, wP[2 * k4 + 0], a0);
                        q0 = fma2(hA.x, wQ[2 * k4 + 0], q0);
                        a1 = fma2(hA.y, wP[2 * k4 + 1], a1);
                        q1 = fma2(hA.y, wQ[2 * k4 + 1], q1);
                        a2 = fma2(hB.x, wP[2 * k4 + 2], a2);
                        q2 = fma2(hB.x, wQ[2 * k4 + 2], q2);
                        a3 = fma2(hB.y, wP[2 * k4 + 3], a3);
                        q3 = fma2(hB.y, wQ[2 * k4 + 3], q3);
                    }
                    a0 = add2(add2(a0, a1), add2(a2, a3));
                    q0 = add2(add2(q0, q1), add2(q2, q3));
                    float2 sa = upk2(a0);
                    float2 sq = upk2(q0);
                    // Wx1 . h0[t-1]  (consumed by L1 at u = t-2, parity u&1)
                    xbuf[(t + 1) & 1][g] = sq.x + sq.y;
                    if (t < S_) {
                        float xv = xwbuf[j];
                        int tn = t + 4;
                        if (tn < S_) xwbuf[j] = xwb[(size_t)tn * G4_];
                        float pre = sa.x + sa.y + xv;
                        gbuf0[g] = (gtype == 2) ? tanh_fast(pre) : sig_fast(pre);
                    }
                }
            } else {
                const int u = t - 2;
                if (u >= 0 && u < S_) {
                    // h1[u-1] lives in h1buf[(u+1)&1]
                    const ulonglong2* h4 =
                        reinterpret_cast<const ulonglong2*>(h1buf[(u + 1) & 1]);
                    ull a0 = 0, a1 = 0, a2 = 0, a3 = 0;
                    ull q0 = 0, q1 = 0, q2 = 0, q3 = 0;
#pragma unroll
                    for (int k4 = 0; k4 < 16; k4 += 2) {
                        ulonglong2 hA = h4[k4];
                        ulonglong2 hB = h4[k4 + 1];
                        a0 = fma2(hA.x, wP[2 * k4 + 0], a0);
                        q0 = fma2(hA.x, wQ[2 * k4 + 0], q0);
                        a1 = fma2(hA.y, wP[2 * k4 + 1], a1);
                        q1 = fma2(hA.y, wQ[2 * k4 + 1], q1);
                        a2 = fma2(hB.x, wP[2 * k4 + 2], a2);
                        q2 = fma2(hB.x, wQ[2 * k4 + 2], q2);
                        a3 = fma2(hB.y, wP[2 * k4 + 3], a3);
                        q3 = fma2(hB.y, wQ[2 * k4 + 3], q3);
                    }
                    a0 = add2(add2(a0, a1), add2(a2, a3));
                    q0 = add2(add2(q0, q1), add2(q2, q3));
                    float2 sa = upk2(a0);
                    float2 sq = upk2(q0);
                    float pre0 = sa.x + sa.y + xbuf[u & 1][i] + b1a;
                    float pre1 = sq.x + sq.y + xbuf[u & 1][i + 128] + b1b;
                    gbuf1[i] = sig_fast(pre0);                  // cols 0..127: i,f
                    gbuf1[i + 128] =
                        (i < 64) ? tanh_fast(pre1) : sig_fast(pre1); // g,o
                }
            }
            __syncthreads();

            if (isL0) {
                if (g < F_ && t < S_) {
                    float iv = gbuf0[g];
                    float fv = gbuf0[g + 64];
                    float gg = gbuf0[g + 128];
                    float ov = gbuf0[g + 192];
                    c_reg = fv * c_reg + iv * gg;
                    h0buf[t & 1][g] = ov * tanh_fast(c_reg);
                }
            } else {
                const int u = t - 2;
                if (i < F_ && u >= 0 && u < S_) {
                    float iv = gbuf1[i];
                    float fv = gbuf1[i + 64];
                    float gg = gbuf1[i + 128];
                    float ov = gbuf1[i + 192];
                    c_reg = fv * c_reg + iv * gg;
                    h1buf[u & 1][i] = ov * tanh_fast(c_reg);
                }
            }
            __syncthreads();
        }
    }

    if (!isL0 && i < F_) c_final[b * F_ + i] = c_reg;
}

// ---------------------------------------------------------------------------
// Tiny dense head
// ---------------------------------------------------------------------------
__global__ void dense_head(const float* __restrict__ cf,
                           const float* __restrict__ wd,
                           const float* __restrict__ bd,
                           float* __restrict__ out) {
    int t = threadIdx.x;
    if (t >= B_ * 10) return;
    int b = t / 10, n = t % 10;
    float s = bd[n];
#pragma unroll
    for (int k = 0; k < F_; k++) s += cf[b * F_ + k] * wd[k * 10 + n];
    out[b * 10 + n] = s;
}

// ---------------------------------------------------------------------------
extern "C" void kernel_launch(void* const* d_in, const int* in_sizes, int n_in,
                              void* d_out, int out_size) {
    const float* x       = (const float*)d_in[0];
    const float* conv_w0 = (const float*)d_in[1];
    const float* conv_b0 = (const float*)d_in[2];
    const float* conv_w1 = (const float*)d_in[3];
    const float* conv_b1 = (const float*)d_in[4];
    const float* conv_w2 = (const float*)d_in[5];
    const float* conv_b2 = (const float*)d_in[6];
    const float* Wx0     = (const float*)d_in[7];
    const float* Wh0     = (const float*)d_in[8];
    const float* b0      = (const float*)d_in[9];
    const float* Wx1     = (const float*)d_in[10];
    const float* Wh1     = (const float*)d_in[11];
    const float* b1      = (const float*)d_in[12];
    const float* dense_w = (const float*)d_in[13];
    const float* dense_b = (const float*)d_in[14];
    float* out = (float*)d_out;

    void *pA, *pB, *pXW0, *pCF;
    cudaGetSymbolAddress(&pA, g_bufA);
    cudaGetSymbolAddress(&pB, g_bufB);
    cudaGetSymbolAddress(&pXW0, g_xw0);
    cudaGetSymbolAddress(&pCF, g_cfinal);
    float* bufA = (float*)pA;
    float* bufB = (float*)pB;
    float* xw0  = (float*)pXW0;
    float* cfin = (float*)pCF;

    dim3 convGrid(S_ / 64, 1, B_);
    dim3 gemmGrid(S_ / 64, G4_ / 64, B_);

    // CNN stack (TK=16: proven low-reg/high-occ for KW=3)
    conv_gemm<3, true, 16><<<convGrid, 256>>>(x, conv_w0, conv_b0, bufA, 128, 64);
    conv_gemm<3, true, 16><<<convGrid, 256>>>(bufA, conv_w1, conv_b1, bufB, 64, 64);
    conv_gemm<3, true, 16><<<convGrid, 256>>>(bufB, conv_w2, conv_b2, bufA, 64, 64);

    // LSTM layer0 input projection (TK=32: verified 316->246us)
    conv_gemm<1, false, 32><<<gemmGrid, 256>>>(bufA, Wx0, b0, xw0, 64, 256);

    // Fused deterministic 2-layer recurrence: 1 CTA/batch, zero cross-CTA sync
    lstm_fused<<<B_, 384>>>(xw0, Wh0, Wx1, b1, Wh1, cfin);

    // Dense head
    dense_head<<<1, B_ * 10>>>(cfin, dense_w, dense_b, out);
}